// round 14
// baseline (speedup 1.0000x reference)
#include <cuda_runtime.h>
#include <cuda_bf16.h>
#include <math.h>

#define MAXN 50000
#define MAXE 800000

typedef unsigned long long u64;

// ---------------- scratch (static device globals; no allocs allowed) ----------------
__device__ int   g_cnt[MAXN];            // zeroed at static init; scan re-zeroes after read
__device__ int   g_off[MAXN + 1];
__device__ int   g_cursor[MAXN];
__device__ volatile u64 g_state[64];     // lookback states; zeroed by k_count block 0
__device__ float g_dis[MAXN];
__device__ int2  g_csr[MAXE];            // {src row, float bits of dis[src]}
__device__ float g_xw1[(size_t)MAXN * 64];  // x@W1 (raw)
__device__ float g_xw2[(size_t)MAXN * 64];  // (relu(agg1)+b1)@W2 (raw)
__device__ float g_z  [(size_t)MAXN * 64];  // layer2 out

// ---------------- streams/events (host-side, created once) ----------------
static cudaStream_t g_s2;
static cudaEvent_t  g_evF, g_evJ;
struct _AthInit {
    _AthInit() {
        cudaStreamCreateWithFlags(&g_s2, cudaStreamNonBlocking);
        cudaEventCreateWithFlags(&g_evF, cudaEventDisableTiming);
        cudaEventCreateWithFlags(&g_evJ, cudaEventDisableTiming);
    }
};
static _AthInit _ath_init;

// ---------------- CSR build ----------------
__global__ void k_count(const int* __restrict__ ei, int nE) {
    if (blockIdx.x == 0 && threadIdx.x < 64) g_state[threadIdx.x] = 0;
    int e = blockIdx.x * blockDim.x + threadIdx.x;
    if (e < nE) atomicAdd(&g_cnt[ei[nE + e]], 1);  // col = target
}

// fused scan: exclusive offsets + cursor init + dis, single kernel.
__global__ void k_scan_fused(int n, int nb) {
    __shared__ int s[1024];
    __shared__ int s_excl;
    __shared__ int r64[2];
    int b = blockIdx.x, t = threadIdx.x;
    int i = b * 1024 + t;
    int v = (i < n) ? g_cnt[i] : 0;
    if (i < n) g_cnt[i] = 0;              // restore invariant for next replay
    s[t] = v;
    __syncthreads();
#pragma unroll
    for (int dd = 1; dd < 1024; dd <<= 1) {
        int x = (t >= dd) ? s[t - dd] : 0;
        __syncthreads();
        s[t] += x;
        __syncthreads();
    }
    int incl = s[t];
    if (t == 1023)
        g_state[b] = (1ull << 32) | (unsigned)incl;   // publish block aggregate
    if (t < 64) {
        int val = 0;
        if (t < b) {
            u64 st;
            do { st = g_state[t]; } while (!(st >> 32));
            val = (int)(unsigned)st;
        }
#pragma unroll
        for (int o = 16; o; o >>= 1) val += __shfl_down_sync(0xffffffffu, val, o);
        if ((t & 31) == 0) r64[t >> 5] = val;
    }
    __syncthreads();
    if (t == 0) s_excl = r64[0] + r64[1];
    __syncthreads();
    int ex = s_excl;
    if (i < n) {
        int o = ex + incl - v;
        g_off[i] = o;
        g_cursor[i] = o;
        g_dis[i] = rsqrtf((float)(v + 1));   // deg = in-degree + self-loop
    }
    if (b == nb - 1 && t == 1023) g_off[n] = ex + incl;
}

__global__ void k_scatter(const int* __restrict__ ei, int nE) {
    int e = blockIdx.x * blockDim.x + threadIdx.x;
    if (e < nE) {
        int row = ei[e];
        int col = ei[nE + e];
        int p = atomicAdd(&g_cursor[col], 1);
        g_csr[p] = make_int2(row, __float_as_int(g_dis[row]));
    }
}

// ---------------- tensor-core GEMM with bf16 2-term split ----------------
// D = xh@Wh + xh@Wl + xl@Wh  (fp32 accum; dropped xl@Wl ~ 2^-18 rel)
__device__ __forceinline__ void split_pack(float a, float b, unsigned& hi, unsigned& lo) {
    __nv_bfloat16 ha = __float2bfloat16_rn(a), hb = __float2bfloat16_rn(b);
    float ra = a - __bfloat162float(ha);
    float rb = b - __bfloat162float(hb);
    __nv_bfloat16 la = __float2bfloat16_rn(ra), lb = __float2bfloat16_rn(rb);
    hi = ((unsigned)__bfloat16_as_ushort(hb) << 16) | (unsigned)__bfloat16_as_ushort(ha);
    lo = ((unsigned)__bfloat16_as_ushort(lb) << 16) | (unsigned)__bfloat16_as_ushort(la);
}

__device__ __forceinline__ void ldsm4(unsigned* r, unsigned addr) {
    asm volatile("ldmatrix.sync.aligned.m8n8.x4.shared.b16 {%0,%1,%2,%3}, [%4];"
        : "=r"(r[0]), "=r"(r[1]), "=r"(r[2]), "=r"(r[3]) : "r"(addr));
}
__device__ __forceinline__ void ldsm4t(unsigned* r, unsigned addr) {
    asm volatile("ldmatrix.sync.aligned.m8n8.x4.trans.shared.b16 {%0,%1,%2,%3}, [%4];"
        : "=r"(r[0]), "=r"(r[1]), "=r"(r[2]), "=r"(r[3]) : "r"(addr));
}
__device__ __forceinline__ void mma16816(float* c, const unsigned* a, const unsigned* b) {
    asm volatile(
        "mma.sync.aligned.m16n8k16.row.col.f32.bf16.bf16.f32 "
        "{%0,%1,%2,%3}, {%4,%5,%6,%7}, {%8,%9}, {%0,%1,%2,%3};"
        : "+f"(c[0]), "+f"(c[1]), "+f"(c[2]), "+f"(c[3])
        : "r"(a[0]), "r"(a[1]), "r"(a[2]), "r"(a[3]), "r"(b[0]), "r"(b[1]));
}

// Block tile 128(M) x 64(N), 256 threads = 8 warps (4M x 2N), warp tile 32x32.
// (R8 champion shape: static smem, k-chunk 32, 80 regs, 3 blocks/SM.)
template <int K>
__global__ void __launch_bounds__(256) k_gemm_mma(const float* __restrict__ A,
                                                  const float* __restrict__ W,
                                                  float* __restrict__ out, int n) {
    constexpr int PA = 40;   // bf16 pitch for x tiles (80B: conflict-free ldmatrix)
    constexpr int PB = 72;   // bf16 pitch for w tiles (144B: conflict-free ldmatrix)
    __shared__ __align__(16) __nv_bfloat16 xh[128 * PA], xl[128 * PA];
    __shared__ __align__(16) __nv_bfloat16 wh[32 * PB],  wl[32 * PB];
    int t = threadIdx.x;
    int lane = t & 31, wrp = t >> 5;
    int wm = wrp & 3, wn = wrp >> 2;
    int row0 = blockIdx.x * 128;

    float acc[2][4][4] = {};

    unsigned sxh = (unsigned)__cvta_generic_to_shared(xh);
    unsigned sxl = (unsigned)__cvta_generic_to_shared(xl);
    unsigned swh = (unsigned)__cvta_generic_to_shared(wh);
    unsigned swl = (unsigned)__cvta_generic_to_shared(wl);

    for (int kc = 0; kc < K; kc += 32) {
        // stage x tile: 128 rows x 32 k, convert fp32 -> (hi, lo) bf16
#pragma unroll
        for (int it = 0; it < 4; it++) {
            int v = it * 256 + t;          // 1024 chunks of 4 floats
            int r = v >> 3, ch = v & 7;
            int gr = min(row0 + r, n - 1);
            float4 xv = *(const float4*)(A + (size_t)gr * K + kc + ch * 4);
            uint2 h, l;
            split_pack(xv.x, xv.y, h.x, l.x);
            split_pack(xv.z, xv.w, h.y, l.y);
            *(uint2*)&xh[r * PA + ch * 4] = h;
            *(uint2*)&xl[r * PA + ch * 4] = l;
        }
        // stage w tile: 32 k x 64 cols
#pragma unroll
        for (int it = 0; it < 2; it++) {
            int v = it * 256 + t;          // 512 chunks of 4 floats
            int r = v >> 4, c = v & 15;
            float4 wv = *(const float4*)(W + (size_t)(kc + r) * 64 + c * 4);
            uint2 h, l;
            split_pack(wv.x, wv.y, h.x, l.x);
            split_pack(wv.z, wv.w, h.y, l.y);
            *(uint2*)&wh[r * PB + c * 4] = h;
            *(uint2*)&wl[r * PB + c * 4] = l;
        }
        __syncthreads();

#pragma unroll
        for (int ks = 0; ks < 32; ks += 16) {
            unsigned ah[2][4], al[2][4], bh[2][4], bl[2][4];
#pragma unroll
            for (int mi = 0; mi < 2; mi++) {
                int rrow = wm * 32 + mi * 16 + (lane & 15);
                unsigned off = (unsigned)(rrow * PA + ks) * 2 + (lane >> 4) * 16;
                ldsm4(ah[mi], sxh + off);
                ldsm4(al[mi], sxl + off);
            }
#pragma unroll
            for (int nb = 0; nb < 2; nb++) {
                int kk = ks + (lane & 7) + ((lane >> 3) & 1) * 8;
                int nc = wn * 32 + nb * 16 + (lane >> 4) * 8;
                unsigned off = (unsigned)(kk * PB + nc) * 2;
                ldsm4t(bh[nb], swh + off);
                ldsm4t(bl[nb], swl + off);
            }
#pragma unroll
            for (int mi = 0; mi < 2; mi++)
#pragma unroll
                for (int nb = 0; nb < 2; nb++)
#pragma unroll
                    for (int q = 0; q < 2; q++) {
                        float* c = acc[mi][nb * 2 + q];
                        mma16816(c, ah[mi], &bh[nb][q * 2]);
                        mma16816(c, ah[mi], &bl[nb][q * 2]);
                        mma16816(c, al[mi], &bh[nb][q * 2]);
                    }
        }
        __syncthreads();
    }

#pragma unroll
    for (int mi = 0; mi < 2; mi++) {
#pragma unroll
        for (int nj = 0; nj < 4; nj++) {
            int col = wn * 32 + nj * 8 + (lane & 3) * 2;
            int r0 = row0 + wm * 32 + mi * 16 + (lane >> 2);
            if (r0 < n)
                *(float2*)(out + (size_t)r0 * 64 + col) =
                    make_float2(acc[mi][nj][0], acc[mi][nj][1]);
            int r1 = r0 + 8;
            if (r1 < n)
                *(float2*)(out + (size_t)r1 * 64 + col) =
                    make_float2(acc[mi][nj][2], acc[mi][nj][3]);
        }
    }
}

// ---------------- Fused aggregate-1 + GEMM2 ----------------
// Per node i: h = relu(dis[i]*(sum_in xw1[row]*dis[row] + xw1[i]*dis[i]) + b1)
// then xw2[i] = h @ W2  (64x64, in-warp fp32, W2 preloaded to smem).
__global__ void k_agg1_gemm2(const float* __restrict__ in, float* __restrict__ out,
                             const float* __restrict__ b1, const float* __restrict__ W2,
                             int n) {
    __shared__ float2 w2s[64][32];   // w2s[k][c2] = (W2[k][2c2], W2[k][2c2+1])
    int t = threadIdx.x;
    for (int i = t; i < 2048; i += 256)
        ((float2*)w2s)[i] = ((const float2*)W2)[i];
    __syncthreads();

    int node = blockIdx.x * 8 + (t >> 5);
    int lane = t & 31;
    if (node >= n) return;
    const float2* inp = (const float2*)in;
    float d = g_dis[node];
    float2 acc = inp[(size_t)node * 32 + lane];
    acc.x *= d; acc.y *= d;                     // self-loop
    int s = g_off[node], e = g_off[node + 1];
    for (int base = s; base < e; base += 32) {
        int idx = base + lane;
        int2 pr = (idx < e) ? g_csr[idx] : make_int2(0, 0);
        int cnt = min(32, e - base);
        for (int j = 0; j < cnt; j++) {
            int row  = __shfl_sync(0xffffffffu, pr.x, j);
            float dw = __int_as_float(__shfl_sync(0xffffffffu, pr.y, j));
            float2 v = inp[(size_t)row * 32 + lane];
            acc.x = fmaf(v.x, dw, acc.x);
            acc.y = fmaf(v.y, dw, acc.y);
        }
    }
    float2 bv = ((const float2*)b1)[lane];
    float hx = fmaxf(fmaf(d, acc.x, bv.x), 0.f);
    float hy = fmaxf(fmaf(d, acc.y, bv.y), 0.f);

    // in-warp GEMM2: out[2lane,2lane+1] = sum_k h[k]*W2[k][...]
    float ox = 0.f, oy = 0.f;
#pragma unroll
    for (int src = 0; src < 32; src++) {
        float ax = __shfl_sync(0xffffffffu, hx, src);   // h[2src]
        float ay = __shfl_sync(0xffffffffu, hy, src);   // h[2src+1]
        float2 wa = w2s[2 * src][lane];
        float2 wb = w2s[2 * src + 1][lane];
        ox = fmaf(ax, wa.x, ox); oy = fmaf(ax, wa.y, oy);
        ox = fmaf(ay, wb.x, ox); oy = fmaf(ay, wb.y, oy);
    }
    ((float2*)out)[(size_t)node * 32 + lane] = make_float2(ox, oy);
}

// ---------------- Aggregation layer 2 (R8 simple: warp per node) ----------------
__global__ void k_aggregate(const float* __restrict__ in, float* __restrict__ out,
                            const float* __restrict__ bias, int n) {
    int node = blockIdx.x * 8 + (threadIdx.x >> 5);
    int lane = threadIdx.x & 31;
    if (node >= n) return;
    const float2* inp = (const float2*)in;
    float d = g_dis[node];
    float2 acc = inp[(size_t)node * 32 + lane];
    acc.x *= d; acc.y *= d;                     // self-loop
    int s = g_off[node], e = g_off[node + 1];
    for (int base = s; base < e; base += 32) {
        int idx = base + lane;
        int2 pr = (idx < e) ? g_csr[idx] : make_int2(0, 0);
        int cnt = min(32, e - base);
        for (int j = 0; j < cnt; j++) {
            int row  = __shfl_sync(0xffffffffu, pr.x, j);
            float dw = __int_as_float(__shfl_sync(0xffffffffu, pr.y, j));
            float2 v = inp[(size_t)row * 32 + lane];
            acc.x = fmaf(v.x, dw, acc.x);
            acc.y = fmaf(v.y, dw, acc.y);
        }
    }
    float2 bv = ((const float2*)bias)[lane];
    float2 o;
    o.x = fmaf(d, acc.x, bv.x);
    o.y = fmaf(d, acc.y, bv.y);
    ((float2*)out)[(size_t)node * 32 + lane] = o;
}

// ---------------- Decode: out[e] = dot(z[src], z[dst]) ----------------
__global__ void k_decode(const int* __restrict__ eli, const float* __restrict__ z,
                         float* __restrict__ out, int nL) {
    int w = blockIdx.x * 8 + (threadIdx.x >> 5);
    int lane = threadIdx.x & 31;
    if (w >= nL) return;
    int s = eli[w];
    int d = eli[nL + w];
    const float2* z2 = (const float2*)z;
    float2 a = z2[(size_t)s * 32 + lane];
    float2 b = z2[(size_t)d * 32 + lane];
    float p = a.x * b.x + a.y * b.y;
#pragma unroll
    for (int o = 16; o > 0; o >>= 1) p += __shfl_down_sync(0xffffffffu, p, o);
    if (lane == 0) out[w] = p;
}

// ---------------- launch ----------------
extern "C" void kernel_launch(void* const* d_in, const int* in_sizes, int n_in,
                              void* d_out, int out_size) {
    const float* x   = (const float*)d_in[0];
    const int*   ei  = (const int*)  d_in[1];
    const int*   eli = (const int*)  d_in[2];
    const float* W1  = (const float*)d_in[3];
    const float* b1  = (const float*)d_in[4];
    const float* W2  = (const float*)d_in[5];
    const float* b2  = (const float*)d_in[6];
    float* out = (float*)d_out;

    int n  = in_sizes[0] / 256;
    int nE = in_sizes[1] / 2;
    int nL = in_sizes[2] / 2;

    void *p_xw1, *p_xw2, *p_z;
    cudaGetSymbolAddress(&p_xw1, g_xw1);
    cudaGetSymbolAddress(&p_xw2, g_xw2);
    cudaGetSymbolAddress(&p_z,   g_z);

    // Fork: CSR build on side stream, GEMM1 concurrently on main stream.
    cudaEventRecord(g_evF, 0);
    cudaStreamWaitEvent(g_s2, g_evF, 0);

    k_count<<<(nE + 255) / 256, 256, 0, g_s2>>>(ei, nE);
    int nb = (n + 1023) / 1024;
    k_scan_fused<<<nb, 1024, 0, g_s2>>>(n, nb);
    k_scatter<<<(nE + 255) / 256, 256, 0, g_s2>>>(ei, nE);
    cudaEventRecord(g_evJ, g_s2);

    int gb = (n + 127) / 128;
    k_gemm_mma<256><<<gb, 256>>>(x, W1, (float*)p_xw1, n);   // concurrent with CSR

    // Join
    cudaStreamWaitEvent(0, g_evJ, 0);

    // layer 1 aggregate + in-warp GEMM2 (h never materialized)
    k_agg1_gemm2<<<(n + 7) / 8, 256>>>((const float*)p_xw1, (float*)p_xw2, b1, W2, n);
    // layer 2 aggregate
    k_aggregate<<<(n + 7) / 8, 256>>>((const float*)p_xw2, (float*)p_z, b2, n);
    // decode
    k_decode<<<(nL + 7) / 8, 256>>>(eli, (const float*)p_z, out, nL);
}

// round 15
// speedup vs baseline: 1.2394x; 1.2394x over previous
#include <cuda_runtime.h>
#include <cuda_bf16.h>
#include <math.h>

#define MAXN 50000
#define MAXE 800000

typedef unsigned long long u64;

// ---------------- scratch (static device globals; no allocs allowed) ----------------
__device__ int   g_cnt[MAXN];            // zeroed at static init; scan re-zeroes after read
__device__ int   g_off[MAXN + 1];
__device__ int   g_cursor[MAXN];
__device__ volatile u64 g_state[64];     // lookback states; zeroed by k_count block 0
__device__ float g_dis[MAXN];
__device__ int2  g_csr[MAXE];            // {src row, float bits of dis[src]}
__device__ float g_xw1[(size_t)MAXN * 64];  // x@W1 (raw)
__device__ float g_h  [(size_t)MAXN * 64];  // relu(layer1)
__device__ float g_xw2[(size_t)MAXN * 64];  // h@W2 (raw)
__device__ float g_z  [(size_t)MAXN * 64];  // layer2 out

// ---------------- streams/events (host-side, created once) ----------------
static cudaStream_t g_s2;
static cudaEvent_t  g_evF, g_evJ;
struct _AthInit {
    _AthInit() {
        cudaStreamCreateWithFlags(&g_s2, cudaStreamNonBlocking);
        cudaEventCreateWithFlags(&g_evF, cudaEventDisableTiming);
        cudaEventCreateWithFlags(&g_evJ, cudaEventDisableTiming);
    }
};
static _AthInit _ath_init;

// ---------------- CSR build ----------------
__global__ void k_count(const int* __restrict__ ei, int nE) {
    if (blockIdx.x == 0 && threadIdx.x < 64) g_state[threadIdx.x] = 0;
    int e = blockIdx.x * blockDim.x + threadIdx.x;
    if (e < nE) atomicAdd(&g_cnt[ei[nE + e]], 1);  // col = target
}

// fused scan: exclusive offsets + cursor init + dis, single kernel.
__global__ void k_scan_fused(int n, int nb) {
    __shared__ int s[1024];
    __shared__ int s_excl;
    __shared__ int r64[2];
    int b = blockIdx.x, t = threadIdx.x;
    int i = b * 1024 + t;
    int v = (i < n) ? g_cnt[i] : 0;
    if (i < n) g_cnt[i] = 0;              // restore invariant for next replay
    s[t] = v;
    __syncthreads();
#pragma unroll
    for (int dd = 1; dd < 1024; dd <<= 1) {
        int x = (t >= dd) ? s[t - dd] : 0;
        __syncthreads();
        s[t] += x;
        __syncthreads();
    }
    int incl = s[t];
    if (t == 1023)
        g_state[b] = (1ull << 32) | (unsigned)incl;   // publish block aggregate
    if (t < 64) {
        int val = 0;
        if (t < b) {
            u64 st;
            do { st = g_state[t]; } while (!(st >> 32));
            val = (int)(unsigned)st;
        }
#pragma unroll
        for (int o = 16; o; o >>= 1) val += __shfl_down_sync(0xffffffffu, val, o);
        if ((t & 31) == 0) r64[t >> 5] = val;
    }
    __syncthreads();
    if (t == 0) s_excl = r64[0] + r64[1];
    __syncthreads();
    int ex = s_excl;
    if (i < n) {
        int o = ex + incl - v;
        g_off[i] = o;
        g_cursor[i] = o;
        g_dis[i] = rsqrtf((float)(v + 1));   // deg = in-degree + self-loop
    }
    if (b == nb - 1 && t == 1023) g_off[n] = ex + incl;
}

__global__ void k_scatter(const int* __restrict__ ei, int nE) {
    int e = blockIdx.x * blockDim.x + threadIdx.x;
    if (e < nE) {
        int row = ei[e];
        int col = ei[nE + e];
        int p = atomicAdd(&g_cursor[col], 1);
        g_csr[p] = make_int2(row, __float_as_int(g_dis[row]));
    }
}

// ---------------- tensor-core GEMM with bf16 2-term split ----------------
// D = xh@Wh + xh@Wl + xl@Wh  (fp32 accum; dropped xl@Wl ~ 2^-18 rel)
__device__ __forceinline__ void split_pack(float a, float b, unsigned& hi, unsigned& lo) {
    __nv_bfloat16 ha = __float2bfloat16_rn(a), hb = __float2bfloat16_rn(b);
    float ra = a - __bfloat162float(ha);
    float rb = b - __bfloat162float(hb);
    __nv_bfloat16 la = __float2bfloat16_rn(ra), lb = __float2bfloat16_rn(rb);
    hi = ((unsigned)__bfloat16_as_ushort(hb) << 16) | (unsigned)__bfloat16_as_ushort(ha);
    lo = ((unsigned)__bfloat16_as_ushort(lb) << 16) | (unsigned)__bfloat16_as_ushort(la);
}

__device__ __forceinline__ void ldsm4(unsigned* r, unsigned addr) {
    asm volatile("ldmatrix.sync.aligned.m8n8.x4.shared.b16 {%0,%1,%2,%3}, [%4];"
        : "=r"(r[0]), "=r"(r[1]), "=r"(r[2]), "=r"(r[3]) : "r"(addr));
}
__device__ __forceinline__ void ldsm4t(unsigned* r, unsigned addr) {
    asm volatile("ldmatrix.sync.aligned.m8n8.x4.trans.shared.b16 {%0,%1,%2,%3}, [%4];"
        : "=r"(r[0]), "=r"(r[1]), "=r"(r[2]), "=r"(r[3]) : "r"(addr));
}
__device__ __forceinline__ void mma16816(float* c, const unsigned* a, const unsigned* b) {
    asm volatile(
        "mma.sync.aligned.m16n8k16.row.col.f32.bf16.bf16.f32 "
        "{%0,%1,%2,%3}, {%4,%5,%6,%7}, {%8,%9}, {%0,%1,%2,%3};"
        : "+f"(c[0]), "+f"(c[1]), "+f"(c[2]), "+f"(c[3])
        : "r"(a[0]), "r"(a[1]), "r"(a[2]), "r"(a[3]), "r"(b[0]), "r"(b[1]));
}

// Block tile 128(M) x 64(N), 256 threads = 8 warps (4M x 2N), warp tile 32x32.
// (R8 champion shape: static smem, k-chunk 32, 80 regs, 3 blocks/SM.)
template <int K>
__global__ void __launch_bounds__(256) k_gemm_mma(const float* __restrict__ A,
                                                  const float* __restrict__ W,
                                                  float* __restrict__ out, int n) {
    constexpr int PA = 40;   // bf16 pitch for x tiles (80B: conflict-free ldmatrix)
    constexpr int PB = 72;   // bf16 pitch for w tiles (144B: conflict-free ldmatrix)
    __shared__ __align__(16) __nv_bfloat16 xh[128 * PA], xl[128 * PA];
    __shared__ __align__(16) __nv_bfloat16 wh[32 * PB],  wl[32 * PB];
    int t = threadIdx.x;
    int lane = t & 31, wrp = t >> 5;
    int wm = wrp & 3, wn = wrp >> 2;
    int row0 = blockIdx.x * 128;

    float acc[2][4][4] = {};

    unsigned sxh = (unsigned)__cvta_generic_to_shared(xh);
    unsigned sxl = (unsigned)__cvta_generic_to_shared(xl);
    unsigned swh = (unsigned)__cvta_generic_to_shared(wh);
    unsigned swl = (unsigned)__cvta_generic_to_shared(wl);

    for (int kc = 0; kc < K; kc += 32) {
        // stage x tile: 128 rows x 32 k, convert fp32 -> (hi, lo) bf16
#pragma unroll
        for (int it = 0; it < 4; it++) {
            int v = it * 256 + t;          // 1024 chunks of 4 floats
            int r = v >> 3, ch = v & 7;
            int gr = min(row0 + r, n - 1);
            float4 xv = *(const float4*)(A + (size_t)gr * K + kc + ch * 4);
            uint2 h, l;
            split_pack(xv.x, xv.y, h.x, l.x);
            split_pack(xv.z, xv.w, h.y, l.y);
            *(uint2*)&xh[r * PA + ch * 4] = h;
            *(uint2*)&xl[r * PA + ch * 4] = l;
        }
        // stage w tile: 32 k x 64 cols
#pragma unroll
        for (int it = 0; it < 2; it++) {
            int v = it * 256 + t;          // 512 chunks of 4 floats
            int r = v >> 4, c = v & 15;
            float4 wv = *(const float4*)(W + (size_t)(kc + r) * 64 + c * 4);
            uint2 h, l;
            split_pack(wv.x, wv.y, h.x, l.x);
            split_pack(wv.z, wv.w, h.y, l.y);
            *(uint2*)&wh[r * PB + c * 4] = h;
            *(uint2*)&wl[r * PB + c * 4] = l;
        }
        __syncthreads();

#pragma unroll
        for (int ks = 0; ks < 32; ks += 16) {
            unsigned ah[2][4], al[2][4], bh[2][4], bl[2][4];
#pragma unroll
            for (int mi = 0; mi < 2; mi++) {
                int rrow = wm * 32 + mi * 16 + (lane & 15);
                unsigned off = (unsigned)(rrow * PA + ks) * 2 + (lane >> 4) * 16;
                ldsm4(ah[mi], sxh + off);
                ldsm4(al[mi], sxl + off);
            }
#pragma unroll
            for (int nb = 0; nb < 2; nb++) {
                int kk = ks + (lane & 7) + ((lane >> 3) & 1) * 8;
                int nc = wn * 32 + nb * 16 + (lane >> 4) * 8;
                unsigned off = (unsigned)(kk * PB + nc) * 2;
                ldsm4t(bh[nb], swh + off);
                ldsm4t(bl[nb], swl + off);
            }
#pragma unroll
            for (int mi = 0; mi < 2; mi++)
#pragma unroll
                for (int nb = 0; nb < 2; nb++)
#pragma unroll
                    for (int q = 0; q < 2; q++) {
                        float* c = acc[mi][nb * 2 + q];
                        mma16816(c, ah[mi], &bh[nb][q * 2]);
                        mma16816(c, ah[mi], &bl[nb][q * 2]);
                        mma16816(c, al[mi], &bh[nb][q * 2]);
                    }
        }
        __syncthreads();
    }

#pragma unroll
    for (int mi = 0; mi < 2; mi++) {
#pragma unroll
        for (int nj = 0; nj < 4; nj++) {
            int col = wn * 32 + nj * 8 + (lane & 3) * 2;
            int r0 = row0 + wm * 32 + mi * 16 + (lane >> 2);
            if (r0 < n)
                *(float2*)(out + (size_t)r0 * 64 + col) =
                    make_float2(acc[mi][nj][0], acc[mi][nj][1]);
            int r1 = r0 + 8;
            if (r1 < n)
                *(float2*)(out + (size_t)r1 * 64 + col) =
                    make_float2(acc[mi][nj][2], acc[mi][nj][3]);
        }
    }
}

// ---------------- Aggregation: paired half-warp, divergence-free ----------------
// One warp serves 2 nodes (lanes 0-15 / 16-31), float4 per lane (256B/row).
// Loop bound = max degree of the pair; slack edges use {row=0, dw=0} (fma x0).
// out[i] = act( dis[i]*( sum_in xw[row]*dis[row] + xw[i]*dis[i] ) + b )
__global__ void k_aggregate(const float* __restrict__ in, float* __restrict__ out,
                            const float* __restrict__ bias, int n, int relu) {
    int t = threadIdx.x;
    int node = blockIdx.x * 16 + (t >> 4);
    int lane16 = t & 15;
    int vnode = min(node, n - 1);
    const float4* inp4 = (const float4*)in;
    float d = g_dis[vnode];
    float4 acc = inp4[(size_t)vnode * 16 + lane16];
    acc.x *= d; acc.y *= d; acc.z *= d; acc.w *= d;   // self-loop
    int s = g_off[vnode];
    int cnt = g_off[vnode + 1] - s;
    int cntmax = max(cnt, __shfl_xor_sync(0xffffffffu, cnt, 16));
    for (int base = 0; base < cntmax; base += 16) {
        int2 pr = (base + lane16 < cnt) ? g_csr[s + base + lane16] : make_int2(0, 0);
        int m = min(16, cntmax - base);
        for (int j = 0; j < m; j++) {
            int   row = __shfl_sync(0xffffffffu, pr.x, j, 16);
            float dw  = __int_as_float(__shfl_sync(0xffffffffu, pr.y, j, 16));
            float4 v = inp4[(size_t)row * 16 + lane16];
            acc.x = fmaf(v.x, dw, acc.x);
            acc.y = fmaf(v.y, dw, acc.y);
            acc.z = fmaf(v.z, dw, acc.z);
            acc.w = fmaf(v.w, dw, acc.w);
        }
    }
    float4 bv = ((const float4*)bias)[lane16];
    float4 o;
    o.x = fmaf(d, acc.x, bv.x);
    o.y = fmaf(d, acc.y, bv.y);
    o.z = fmaf(d, acc.z, bv.z);
    o.w = fmaf(d, acc.w, bv.w);
    if (relu) {
        o.x = fmaxf(o.x, 0.f); o.y = fmaxf(o.y, 0.f);
        o.z = fmaxf(o.z, 0.f); o.w = fmaxf(o.w, 0.f);
    }
    if (node < n)
        ((float4*)out)[(size_t)node * 16 + lane16] = o;
}

// ---------------- Decode: out[e] = dot(z[src], z[dst]) ----------------
__global__ void k_decode(const int* __restrict__ eli, const float* __restrict__ z,
                         float* __restrict__ out, int nL) {
    int w = blockIdx.x * 8 + (threadIdx.x >> 5);
    int lane = threadIdx.x & 31;
    if (w >= nL) return;
    int s = eli[w];
    int d = eli[nL + w];
    const float2* z2 = (const float2*)z;
    float2 a = z2[(size_t)s * 32 + lane];
    float2 b = z2[(size_t)d * 32 + lane];
    float p = a.x * b.x + a.y * b.y;
#pragma unroll
    for (int o = 16; o > 0; o >>= 1) p += __shfl_down_sync(0xffffffffu, p, o);
    if (lane == 0) out[w] = p;
}

// ---------------- launch ----------------
extern "C" void kernel_launch(void* const* d_in, const int* in_sizes, int n_in,
                              void* d_out, int out_size) {
    const float* x   = (const float*)d_in[0];
    const int*   ei  = (const int*)  d_in[1];
    const int*   eli = (const int*)  d_in[2];
    const float* W1  = (const float*)d_in[3];
    const float* b1  = (const float*)d_in[4];
    const float* W2  = (const float*)d_in[5];
    const float* b2  = (const float*)d_in[6];
    float* out = (float*)d_out;

    int n  = in_sizes[0] / 256;
    int nE = in_sizes[1] / 2;
    int nL = in_sizes[2] / 2;

    void *p_xw1, *p_h, *p_xw2, *p_z;
    cudaGetSymbolAddress(&p_xw1, g_xw1);
    cudaGetSymbolAddress(&p_h,   g_h);
    cudaGetSymbolAddress(&p_xw2, g_xw2);
    cudaGetSymbolAddress(&p_z,   g_z);

    // Fork: CSR build on side stream, GEMM1 concurrently on main stream.
    cudaEventRecord(g_evF, 0);
    cudaStreamWaitEvent(g_s2, g_evF, 0);

    k_count<<<(nE + 255) / 256, 256, 0, g_s2>>>(ei, nE);
    int nb = (n + 1023) / 1024;
    k_scan_fused<<<nb, 1024, 0, g_s2>>>(n, nb);
    k_scatter<<<(nE + 255) / 256, 256, 0, g_s2>>>(ei, nE);
    cudaEventRecord(g_evJ, g_s2);

    int gb = (n + 127) / 128;
    k_gemm_mma<256><<<gb, 256>>>(x, W1, (float*)p_xw1, n);   // concurrent with CSR

    // Join
    cudaStreamWaitEvent(0, g_evJ, 0);

    // layer 1 aggregate
    k_aggregate<<<(n + 15) / 16, 256>>>((const float*)p_xw1, (float*)p_h, b1, n, 1);
    // layer 2
    k_gemm_mma<64><<<gb, 256>>>((const float*)p_h, W2, (float*)p_xw2, n);
    k_aggregate<<<(n + 15) / 16, 256>>>((const float*)p_xw2, (float*)p_z, b2, n, 0);
    // decode
    k_decode<<<(nL + 7) / 8, 256>>>(eli, (const float*)p_z, out, nL);
}

// round 16
// speedup vs baseline: 1.2725x; 1.0268x over previous
#include <cuda_runtime.h>
#include <cuda_bf16.h>
#include <cuda_fp16.h>
#include <math.h>

#define MAXN 50000
#define MAXE 800000

typedef unsigned long long u64;

// ---------------- scratch (static device globals; no allocs allowed) ----------------
__device__ int   g_cnt[MAXN];            // zeroed at static init; scan re-zeroes after read
__device__ int   g_off[MAXN + 1];
__device__ int   g_cursor[MAXN];
__device__ volatile u64 g_state[64];     // lookback states; zeroed by k_count block 0
__device__ float g_dis[MAXN];
__device__ int2  g_csr[MAXE];            // {src row, float bits of dis[src]}
__device__ __half g_xw1[(size_t)MAXN * 64]; // x@W1 (fp16, gather-only)
__device__ float  g_h  [(size_t)MAXN * 64]; // relu(layer1) fp32
__device__ __half g_xw2[(size_t)MAXN * 64]; // h@W2 (fp16, gather-only)
__device__ float  g_z  [(size_t)MAXN * 64]; // layer2 out fp32

// ---------------- streams/events (host-side, created once) ----------------
static cudaStream_t g_s2;
static cudaEvent_t  g_evF, g_evJ;
struct _AthInit {
    _AthInit() {
        cudaStreamCreateWithFlags(&g_s2, cudaStreamNonBlocking);
        cudaEventCreateWithFlags(&g_evF, cudaEventDisableTiming);
        cudaEventCreateWithFlags(&g_evJ, cudaEventDisableTiming);
    }
};
static _AthInit _ath_init;

// ---------------- CSR build ----------------
__global__ void k_count(const int* __restrict__ ei, int nE) {
    if (blockIdx.x == 0 && threadIdx.x < 64) g_state[threadIdx.x] = 0;
    int e = blockIdx.x * blockDim.x + threadIdx.x;
    if (e < nE) atomicAdd(&g_cnt[ei[nE + e]], 1);  // col = target
}

// fused scan: exclusive offsets + cursor init + dis, single kernel.
__global__ void k_scan_fused(int n, int nb) {
    __shared__ int s[1024];
    __shared__ int s_excl;
    __shared__ int r64[2];
    int b = blockIdx.x, t = threadIdx.x;
    int i = b * 1024 + t;
    int v = (i < n) ? g_cnt[i] : 0;
    if (i < n) g_cnt[i] = 0;              // restore invariant for next replay
    s[t] = v;
    __syncthreads();
#pragma unroll
    for (int dd = 1; dd < 1024; dd <<= 1) {
        int x = (t >= dd) ? s[t - dd] : 0;
        __syncthreads();
        s[t] += x;
        __syncthreads();
    }
    int incl = s[t];
    if (t == 1023)
        g_state[b] = (1ull << 32) | (unsigned)incl;   // publish block aggregate
    if (t < 64) {
        int val = 0;
        if (t < b) {
            u64 st;
            do { st = g_state[t]; } while (!(st >> 32));
            val = (int)(unsigned)st;
        }
#pragma unroll
        for (int o = 16; o; o >>= 1) val += __shfl_down_sync(0xffffffffu, val, o);
        if ((t & 31) == 0) r64[t >> 5] = val;
    }
    __syncthreads();
    if (t == 0) s_excl = r64[0] + r64[1];
    __syncthreads();
    int ex = s_excl;
    if (i < n) {
        int o = ex + incl - v;
        g_off[i] = o;
        g_cursor[i] = o;
        g_dis[i] = rsqrtf((float)(v + 1));   // deg = in-degree + self-loop
    }
    if (b == nb - 1 && t == 1023) g_off[n] = ex + incl;
}

__global__ void k_scatter(const int* __restrict__ ei, int nE) {
    int e = blockIdx.x * blockDim.x + threadIdx.x;
    if (e < nE) {
        int row = ei[e];
        int col = ei[nE + e];
        int p = atomicAdd(&g_cursor[col], 1);
        g_csr[p] = make_int2(row, __float_as_int(g_dis[row]));
    }
}

// ---------------- tensor-core GEMM with bf16 2-term split ----------------
// D = xh@Wh + xh@Wl + xl@Wh  (fp32 accum; dropped xl@Wl ~ 2^-18 rel)
__device__ __forceinline__ void split_pack(float a, float b, unsigned& hi, unsigned& lo) {
    __nv_bfloat16 ha = __float2bfloat16_rn(a), hb = __float2bfloat16_rn(b);
    float ra = a - __bfloat162float(ha);
    float rb = b - __bfloat162float(hb);
    __nv_bfloat16 la = __float2bfloat16_rn(ra), lb = __float2bfloat16_rn(rb);
    hi = ((unsigned)__bfloat16_as_ushort(hb) << 16) | (unsigned)__bfloat16_as_ushort(ha);
    lo = ((unsigned)__bfloat16_as_ushort(lb) << 16) | (unsigned)__bfloat16_as_ushort(la);
}

__device__ __forceinline__ void ldsm4(unsigned* r, unsigned addr) {
    asm volatile("ldmatrix.sync.aligned.m8n8.x4.shared.b16 {%0,%1,%2,%3}, [%4];"
        : "=r"(r[0]), "=r"(r[1]), "=r"(r[2]), "=r"(r[3]) : "r"(addr));
}
__device__ __forceinline__ void ldsm4t(unsigned* r, unsigned addr) {
    asm volatile("ldmatrix.sync.aligned.m8n8.x4.trans.shared.b16 {%0,%1,%2,%3}, [%4];"
        : "=r"(r[0]), "=r"(r[1]), "=r"(r[2]), "=r"(r[3]) : "r"(addr));
}
__device__ __forceinline__ void mma16816(float* c, const unsigned* a, const unsigned* b) {
    asm volatile(
        "mma.sync.aligned.m16n8k16.row.col.f32.bf16.bf16.f32 "
        "{%0,%1,%2,%3}, {%4,%5,%6,%7}, {%8,%9}, {%0,%1,%2,%3};"
        : "+f"(c[0]), "+f"(c[1]), "+f"(c[2]), "+f"(c[3])
        : "r"(a[0]), "r"(a[1]), "r"(a[2]), "r"(a[3]), "r"(b[0]), "r"(b[1]));
}

// Block tile 128(M) x 64(N), 256 threads = 8 warps (4M x 2N), warp tile 32x32.
// (R8 champion shape.) Output written as fp16 (gather-optimized).
template <int K>
__global__ void __launch_bounds__(256) k_gemm_mma(const float* __restrict__ A,
                                                  const float* __restrict__ W,
                                                  __half* __restrict__ out, int n) {
    constexpr int PA = 40;   // bf16 pitch for x tiles (80B: conflict-free ldmatrix)
    constexpr int PB = 72;   // bf16 pitch for w tiles (144B: conflict-free ldmatrix)
    __shared__ __align__(16) __nv_bfloat16 xh[128 * PA], xl[128 * PA];
    __shared__ __align__(16) __nv_bfloat16 wh[32 * PB],  wl[32 * PB];
    int t = threadIdx.x;
    int lane = t & 31, wrp = t >> 5;
    int wm = wrp & 3, wn = wrp >> 2;
    int row0 = blockIdx.x * 128;

    float acc[2][4][4] = {};

    unsigned sxh = (unsigned)__cvta_generic_to_shared(xh);
    unsigned sxl = (unsigned)__cvta_generic_to_shared(xl);
    unsigned swh = (unsigned)__cvta_generic_to_shared(wh);
    unsigned swl = (unsigned)__cvta_generic_to_shared(wl);

    for (int kc = 0; kc < K; kc += 32) {
        // stage x tile: 128 rows x 32 k, convert fp32 -> (hi, lo) bf16
#pragma unroll
        for (int it = 0; it < 4; it++) {
            int v = it * 256 + t;          // 1024 chunks of 4 floats
            int r = v >> 3, ch = v & 7;
            int gr = min(row0 + r, n - 1);
            float4 xv = *(const float4*)(A + (size_t)gr * K + kc + ch * 4);
            uint2 h, l;
            split_pack(xv.x, xv.y, h.x, l.x);
            split_pack(xv.z, xv.w, h.y, l.y);
            *(uint2*)&xh[r * PA + ch * 4] = h;
            *(uint2*)&xl[r * PA + ch * 4] = l;
        }
        // stage w tile: 32 k x 64 cols
#pragma unroll
        for (int it = 0; it < 2; it++) {
            int v = it * 256 + t;          // 512 chunks of 4 floats
            int r = v >> 4, c = v & 15;
            float4 wv = *(const float4*)(W + (size_t)(kc + r) * 64 + c * 4);
            uint2 h, l;
            split_pack(wv.x, wv.y, h.x, l.x);
            split_pack(wv.z, wv.w, h.y, l.y);
            *(uint2*)&wh[r * PB + c * 4] = h;
            *(uint2*)&wl[r * PB + c * 4] = l;
        }
        __syncthreads();

#pragma unroll
        for (int ks = 0; ks < 32; ks += 16) {
            unsigned ah[2][4], al[2][4], bh[2][4], bl[2][4];
#pragma unroll
            for (int mi = 0; mi < 2; mi++) {
                int rrow = wm * 32 + mi * 16 + (lane & 15);
                unsigned off = (unsigned)(rrow * PA + ks) * 2 + (lane >> 4) * 16;
                ldsm4(ah[mi], sxh + off);
                ldsm4(al[mi], sxl + off);
            }
#pragma unroll
            for (int nb = 0; nb < 2; nb++) {
                int kk = ks + (lane & 7) + ((lane >> 3) & 1) * 8;
                int nc = wn * 32 + nb * 16 + (lane >> 4) * 8;
                unsigned off = (unsigned)(kk * PB + nc) * 2;
                ldsm4t(bh[nb], swh + off);
                ldsm4t(bl[nb], swl + off);
            }
#pragma unroll
            for (int mi = 0; mi < 2; mi++)
#pragma unroll
                for (int nb = 0; nb < 2; nb++)
#pragma unroll
                    for (int q = 0; q < 2; q++) {
                        float* c = acc[mi][nb * 2 + q];
                        mma16816(c, ah[mi], &bh[nb][q * 2]);
                        mma16816(c, ah[mi], &bl[nb][q * 2]);
                        mma16816(c, al[mi], &bh[nb][q * 2]);
                    }
        }
        __syncthreads();
    }

#pragma unroll
    for (int mi = 0; mi < 2; mi++) {
#pragma unroll
        for (int nj = 0; nj < 4; nj++) {
            int col = wn * 32 + nj * 8 + (lane & 3) * 2;
            int r0 = row0 + wm * 32 + mi * 16 + (lane >> 2);
            if (r0 < n)
                *(__half2*)(out + (size_t)r0 * 64 + col) =
                    __floats2half2_rn(acc[mi][nj][0], acc[mi][nj][1]);
            int r1 = r0 + 8;
            if (r1 < n)
                *(__half2*)(out + (size_t)r1 * 64 + col) =
                    __floats2half2_rn(acc[mi][nj][2], acc[mi][nj][3]);
        }
    }
}

// ---------------- Aggregation: paired half-warp, fp16 gather, fp32 math/out ----------------
// One warp serves 2 nodes (lanes 0-15 / 16-31), 4 channels per lane (8B fp16 loads).
// out[i] = act( dis[i]*( sum_in xw[row]*dis[row] + xw[i]*dis[i] ) + b )
__device__ __forceinline__ float4 ld_h4(const uint2* p, size_t idx) {
    uint2 raw = p[idx];
    float2 a = __half22float2(*(__half2*)&raw.x);
    float2 b = __half22float2(*(__half2*)&raw.y);
    return make_float4(a.x, a.y, b.x, b.y);
}

__global__ void k_aggregate(const __half* __restrict__ in, float* __restrict__ out,
                            const float* __restrict__ bias, int n, int relu) {
    int t = threadIdx.x;
    int node = blockIdx.x * 16 + (t >> 4);
    int lane16 = t & 15;
    int vnode = min(node, n - 1);
    const uint2* inp = (const uint2*)in;   // row pitch = 16 uint2 (128B)
    float d = g_dis[vnode];
    float4 acc = ld_h4(inp, (size_t)vnode * 16 + lane16);
    acc.x *= d; acc.y *= d; acc.z *= d; acc.w *= d;   // self-loop
    int s = g_off[vnode];
    int cnt = g_off[vnode + 1] - s;
    int cntmax = max(cnt, __shfl_xor_sync(0xffffffffu, cnt, 16));
    for (int base = 0; base < cntmax; base += 16) {
        int2 pr = (base + lane16 < cnt) ? g_csr[s + base + lane16] : make_int2(0, 0);
        int m = min(16, cntmax - base);
        for (int j = 0; j < m; j++) {
            int   row = __shfl_sync(0xffffffffu, pr.x, j, 16);
            float dw  = __int_as_float(__shfl_sync(0xffffffffu, pr.y, j, 16));
            float4 v = ld_h4(inp, (size_t)row * 16 + lane16);
            acc.x = fmaf(v.x, dw, acc.x);
            acc.y = fmaf(v.y, dw, acc.y);
            acc.z = fmaf(v.z, dw, acc.z);
            acc.w = fmaf(v.w, dw, acc.w);
        }
    }
    float4 bv = ((const float4*)bias)[lane16];
    float4 o;
    o.x = fmaf(d, acc.x, bv.x);
    o.y = fmaf(d, acc.y, bv.y);
    o.z = fmaf(d, acc.z, bv.z);
    o.w = fmaf(d, acc.w, bv.w);
    if (relu) {
        o.x = fmaxf(o.x, 0.f); o.y = fmaxf(o.y, 0.f);
        o.z = fmaxf(o.z, 0.f); o.w = fmaxf(o.w, 0.f);
    }
    if (node < n)
        ((float4*)out)[(size_t)node * 16 + lane16] = o;
}

// ---------------- Decode: out[e] = dot(z[src], z[dst]) ----------------
__global__ void k_decode(const int* __restrict__ eli, const float* __restrict__ z,
                         float* __restrict__ out, int nL) {
    int w = blockIdx.x * 8 + (threadIdx.x >> 5);
    int lane = threadIdx.x & 31;
    if (w >= nL) return;
    int s = eli[w];
    int d = eli[nL + w];
    const float2* z2 = (const float2*)z;
    float2 a = z2[(size_t)s * 32 + lane];
    float2 b = z2[(size_t)d * 32 + lane];
    float p = a.x * b.x + a.y * b.y;
#pragma unroll
    for (int o = 16; o > 0; o >>= 1) p += __shfl_down_sync(0xffffffffu, p, o);
    if (lane == 0) out[w] = p;
}

// ---------------- launch ----------------
extern "C" void kernel_launch(void* const* d_in, const int* in_sizes, int n_in,
                              void* d_out, int out_size) {
    const float* x   = (const float*)d_in[0];
    const int*   ei  = (const int*)  d_in[1];
    const int*   eli = (const int*)  d_in[2];
    const float* W1  = (const float*)d_in[3];
    const float* b1  = (const float*)d_in[4];
    const float* W2  = (const float*)d_in[5];
    const float* b2  = (const float*)d_in[6];
    float* out = (float*)d_out;

    int n  = in_sizes[0] / 256;
    int nE = in_sizes[1] / 2;
    int nL = in_sizes[2] / 2;

    void *p_xw1, *p_h, *p_xw2, *p_z;
    cudaGetSymbolAddress(&p_xw1, g_xw1);
    cudaGetSymbolAddress(&p_h,   g_h);
    cudaGetSymbolAddress(&p_xw2, g_xw2);
    cudaGetSymbolAddress(&p_z,   g_z);

    // Fork: CSR build on side stream, GEMM1 concurrently on main stream.
    cudaEventRecord(g_evF, 0);
    cudaStreamWaitEvent(g_s2, g_evF, 0);

    k_count<<<(nE + 255) / 256, 256, 0, g_s2>>>(ei, nE);
    int nb = (n + 1023) / 1024;
    k_scan_fused<<<nb, 1024, 0, g_s2>>>(n, nb);
    k_scatter<<<(nE + 255) / 256, 256, 0, g_s2>>>(ei, nE);
    cudaEventRecord(g_evJ, g_s2);

    int gb = (n + 127) / 128;
    k_gemm_mma<256><<<gb, 256>>>(x, W1, (__half*)p_xw1, n);   // concurrent with CSR

    // Join
    cudaStreamWaitEvent(0, g_evJ, 0);

    // layer 1 aggregate (fp16 gather -> fp32 h)
    k_aggregate<<<(n + 15) / 16, 256>>>((const __half*)p_xw1, (float*)p_h, b1, n, 1);
    // layer 2
    k_gemm_mma<64><<<gb, 256>>>((const float*)p_h, W2, (__half*)p_xw2, n);
    k_aggregate<<<(n + 15) / 16, 256>>>((const __half*)p_xw2, (float*)p_z, b2, n, 0);
    // decode
    k_decode<<<(nL + 7) / 8, 256>>>(eli, (const float*)p_z, out, nL);
}

// round 17
// speedup vs baseline: 1.4733x; 1.1578x over previous
#include <cuda_runtime.h>
#include <cuda_bf16.h>
#include <cuda_fp16.h>
#include <math.h>

#define MAXN 50000
#define MAXE 800000

typedef unsigned long long u64;

// ---------------- scratch (static device globals; no allocs allowed) ----------------
__device__ int   g_cnt[MAXN];            // zeroed at static init; scan re-zeroes after read
__device__ int   g_off[MAXN + 1];
__device__ int   g_cursor[MAXN];
__device__ volatile u64 g_state[64];     // lookback states; zeroed by k_count block 0
__device__ float g_dis[MAXN];
__device__ int2  g_csr[MAXE];            // {src row, float bits of dis[src]}
__device__ __half g_xw1[(size_t)MAXN * 64]; // x@W1 (fp16, gather-only)
__device__ float  g_h  [(size_t)MAXN * 64]; // relu(layer1) fp32
__device__ __half g_xw2[(size_t)MAXN * 64]; // h@W2 (fp16, gather-only)
__device__ float  g_z  [(size_t)MAXN * 64]; // layer2 out fp32

// ---------------- streams/events (host-side, created once) ----------------
static cudaStream_t g_s2;
static cudaEvent_t  g_evF, g_evJ;
struct _AthInit {
    _AthInit() {
        cudaStreamCreateWithFlags(&g_s2, cudaStreamNonBlocking);
        cudaEventCreateWithFlags(&g_evF, cudaEventDisableTiming);
        cudaEventCreateWithFlags(&g_evJ, cudaEventDisableTiming);
    }
};
static _AthInit _ath_init;

// ---------------- CSR build ----------------
__global__ void k_count(const int* __restrict__ ei, int nE) {
    if (blockIdx.x == 0 && threadIdx.x < 64) g_state[threadIdx.x] = 0;
    int e = blockIdx.x * blockDim.x + threadIdx.x;
    if (e < nE) atomicAdd(&g_cnt[ei[nE + e]], 1);  // col = target
}

// fused scan: exclusive offsets + cursor init + dis, single kernel.
__global__ void k_scan_fused(int n, int nb) {
    __shared__ int s[1024];
    __shared__ int s_excl;
    __shared__ int r64[2];
    int b = blockIdx.x, t = threadIdx.x;
    int i = b * 1024 + t;
    int v = (i < n) ? g_cnt[i] : 0;
    if (i < n) g_cnt[i] = 0;              // restore invariant for next replay
    s[t] = v;
    __syncthreads();
#pragma unroll
    for (int dd = 1; dd < 1024; dd <<= 1) {
        int x = (t >= dd) ? s[t - dd] : 0;
        __syncthreads();
        s[t] += x;
        __syncthreads();
    }
    int incl = s[t];
    if (t == 1023)
        g_state[b] = (1ull << 32) | (unsigned)incl;   // publish block aggregate
    if (t < 64) {
        int val = 0;
        if (t < b) {
            u64 st;
            do { st = g_state[t]; } while (!(st >> 32));
            val = (int)(unsigned)st;
        }
#pragma unroll
        for (int o = 16; o; o >>= 1) val += __shfl_down_sync(0xffffffffu, val, o);
        if ((t & 31) == 0) r64[t >> 5] = val;
    }
    __syncthreads();
    if (t == 0) s_excl = r64[0] + r64[1];
    __syncthreads();
    int ex = s_excl;
    if (i < n) {
        int o = ex + incl - v;
        g_off[i] = o;
        g_cursor[i] = o;
        g_dis[i] = rsqrtf((float)(v + 1));   // deg = in-degree + self-loop
    }
    if (b == nb - 1 && t == 1023) g_off[n] = ex + incl;
}

__global__ void k_scatter(const int* __restrict__ ei, int nE) {
    int e = blockIdx.x * blockDim.x + threadIdx.x;
    if (e < nE) {
        int row = ei[e];
        int col = ei[nE + e];
        int p = atomicAdd(&g_cursor[col], 1);
        g_csr[p] = make_int2(row, __float_as_int(g_dis[row]));
    }
}

// ---------------- tensor-core GEMM with bf16 2-term split ----------------
// D = xh@Wh + xh@Wl + xl@Wh  (fp32 accum; dropped xl@Wl ~ 2^-18 rel)
__device__ __forceinline__ void split_pack(float a, float b, unsigned& hi, unsigned& lo) {
    __nv_bfloat16 ha = __float2bfloat16_rn(a), hb = __float2bfloat16_rn(b);
    float ra = a - __bfloat162float(ha);
    float rb = b - __bfloat162float(hb);
    __nv_bfloat16 la = __float2bfloat16_rn(ra), lb = __float2bfloat16_rn(rb);
    hi = ((unsigned)__bfloat16_as_ushort(hb) << 16) | (unsigned)__bfloat16_as_ushort(ha);
    lo = ((unsigned)__bfloat16_as_ushort(lb) << 16) | (unsigned)__bfloat16_as_ushort(la);
}

__device__ __forceinline__ void ldsm4(unsigned* r, unsigned addr) {
    asm volatile("ldmatrix.sync.aligned.m8n8.x4.shared.b16 {%0,%1,%2,%3}, [%4];"
        : "=r"(r[0]), "=r"(r[1]), "=r"(r[2]), "=r"(r[3]) : "r"(addr));
}
__device__ __forceinline__ void ldsm4t(unsigned* r, unsigned addr) {
    asm volatile("ldmatrix.sync.aligned.m8n8.x4.trans.shared.b16 {%0,%1,%2,%3}, [%4];"
        : "=r"(r[0]), "=r"(r[1]), "=r"(r[2]), "=r"(r[3]) : "r"(addr));
}
__device__ __forceinline__ void mma16816(float* c, const unsigned* a, const unsigned* b) {
    asm volatile(
        "mma.sync.aligned.m16n8k16.row.col.f32.bf16.bf16.f32 "
        "{%0,%1,%2,%3}, {%4,%5,%6,%7}, {%8,%9}, {%0,%1,%2,%3};"
        : "+f"(c[0]), "+f"(c[1]), "+f"(c[2]), "+f"(c[3])
        : "r"(a[0]), "r"(a[1]), "r"(a[2]), "r"(a[3]), "r"(b[0]), "r"(b[1]));
}

// Block tile 128(M) x 64(N), 256 threads = 8 warps (4M x 2N), warp tile 32x32.
// (R8 champion shape.) Output written as fp16 (gather-optimized).
template <int K>
__global__ void __launch_bounds__(256) k_gemm_mma(const float* __restrict__ A,
                                                  const float* __restrict__ W,
                                                  __half* __restrict__ out, int n) {
    constexpr int PA = 40;   // bf16 pitch for x tiles (80B: conflict-free ldmatrix)
    constexpr int PB = 72;   // bf16 pitch for w tiles (144B: conflict-free ldmatrix)
    __shared__ __align__(16) __nv_bfloat16 xh[128 * PA], xl[128 * PA];
    __shared__ __align__(16) __nv_bfloat16 wh[32 * PB],  wl[32 * PB];
    int t = threadIdx.x;
    int lane = t & 31, wrp = t >> 5;
    int wm = wrp & 3, wn = wrp >> 2;
    int row0 = blockIdx.x * 128;

    float acc[2][4][4] = {};

    unsigned sxh = (unsigned)__cvta_generic_to_shared(xh);
    unsigned sxl = (unsigned)__cvta_generic_to_shared(xl);
    unsigned swh = (unsigned)__cvta_generic_to_shared(wh);
    unsigned swl = (unsigned)__cvta_generic_to_shared(wl);

    for (int kc = 0; kc < K; kc += 32) {
        // stage x tile: 128 rows x 32 k, convert fp32 -> (hi, lo) bf16
#pragma unroll
        for (int it = 0; it < 4; it++) {
            int v = it * 256 + t;          // 1024 chunks of 4 floats
            int r = v >> 3, ch = v & 7;
            int gr = min(row0 + r, n - 1);
            float4 xv = *(const float4*)(A + (size_t)gr * K + kc + ch * 4);
            uint2 h, l;
            split_pack(xv.x, xv.y, h.x, l.x);
            split_pack(xv.z, xv.w, h.y, l.y);
            *(uint2*)&xh[r * PA + ch * 4] = h;
            *(uint2*)&xl[r * PA + ch * 4] = l;
        }
        // stage w tile: 32 k x 64 cols
#pragma unroll
        for (int it = 0; it < 2; it++) {
            int v = it * 256 + t;          // 512 chunks of 4 floats
            int r = v >> 4, c = v & 15;
            float4 wv = *(const float4*)(W + (size_t)(kc + r) * 64 + c * 4);
            uint2 h, l;
            split_pack(wv.x, wv.y, h.x, l.x);
            split_pack(wv.z, wv.w, h.y, l.y);
            *(uint2*)&wh[r * PB + c * 4] = h;
            *(uint2*)&wl[r * PB + c * 4] = l;
        }
        __syncthreads();

#pragma unroll
        for (int ks = 0; ks < 32; ks += 16) {
            unsigned ah[2][4], al[2][4], bh[2][4], bl[2][4];
#pragma unroll
            for (int mi = 0; mi < 2; mi++) {
                int rrow = wm * 32 + mi * 16 + (lane & 15);
                unsigned off = (unsigned)(rrow * PA + ks) * 2 + (lane >> 4) * 16;
                ldsm4(ah[mi], sxh + off);
                ldsm4(al[mi], sxl + off);
            }
#pragma unroll
            for (int nb = 0; nb < 2; nb++) {
                int kk = ks + (lane & 7) + ((lane >> 3) & 1) * 8;
                int nc = wn * 32 + nb * 16 + (lane >> 4) * 8;
                unsigned off = (unsigned)(kk * PB + nc) * 2;
                ldsm4t(bh[nb], swh + off);
                ldsm4t(bl[nb], swl + off);
            }
#pragma unroll
            for (int mi = 0; mi < 2; mi++)
#pragma unroll
                for (int nb = 0; nb < 2; nb++)
#pragma unroll
                    for (int q = 0; q < 2; q++) {
                        float* c = acc[mi][nb * 2 + q];
                        mma16816(c, ah[mi], &bh[nb][q * 2]);
                        mma16816(c, ah[mi], &bl[nb][q * 2]);
                        mma16816(c, al[mi], &bh[nb][q * 2]);
                    }
        }
        __syncthreads();
    }

#pragma unroll
    for (int mi = 0; mi < 2; mi++) {
#pragma unroll
        for (int nj = 0; nj < 4; nj++) {
            int col = wn * 32 + nj * 8 + (lane & 3) * 2;
            int r0 = row0 + wm * 32 + mi * 16 + (lane >> 2);
            if (r0 < n)
                *(__half2*)(out + (size_t)r0 * 64 + col) =
                    __floats2half2_rn(acc[mi][nj][0], acc[mi][nj][1]);
            int r1 = r0 + 8;
            if (r1 < n)
                *(__half2*)(out + (size_t)r1 * 64 + col) =
                    __floats2half2_rn(acc[mi][nj][2], acc[mi][nj][3]);
        }
    }
}

// ---------------- Aggregation: 8-lane groups (4 nodes/warp), fp16 uint4 gathers ----------------
// One LDG.128 warp-instruction gathers 4 rows (one per group); 2-deep unroll -> MLP=2.
// out[i] = act( dis[i]*( sum_in xw[row]*dis[row] + xw[i]*dis[i] ) + b )
__device__ __forceinline__ void fma8(float* a, uint4 v, float dw) {
    float2 p0 = __half22float2(*(__half2*)&v.x);
    float2 p1 = __half22float2(*(__half2*)&v.y);
    float2 p2 = __half22float2(*(__half2*)&v.z);
    float2 p3 = __half22float2(*(__half2*)&v.w);
    a[0] = fmaf(p0.x, dw, a[0]); a[1] = fmaf(p0.y, dw, a[1]);
    a[2] = fmaf(p1.x, dw, a[2]); a[3] = fmaf(p1.y, dw, a[3]);
    a[4] = fmaf(p2.x, dw, a[4]); a[5] = fmaf(p2.y, dw, a[5]);
    a[6] = fmaf(p3.x, dw, a[6]); a[7] = fmaf(p3.y, dw, a[7]);
}

__global__ void k_aggregate(const __half* __restrict__ in, float* __restrict__ out,
                            const float* __restrict__ bias, int n, int relu) {
    int t = threadIdx.x;
    int node = blockIdx.x * 32 + (t >> 3);   // 256 threads = 32 nodes/block
    int lane8 = t & 7;
    int vnode = min(node, n - 1);
    const uint4* inp = (const uint4*)in;     // row pitch = 8 uint4 (128B)
    float d = g_dis[vnode];
    float acc[8] = {}, acc2[8] = {};
    fma8(acc, inp[(size_t)vnode * 8 + lane8], d);   // self-loop: xw[i]*dis[i]
    int s = g_off[vnode];
    int cnt = g_off[vnode + 1] - s;
    int cm = cnt;
    cm = max(cm, __shfl_xor_sync(0xffffffffu, cm, 8));
    cm = max(cm, __shfl_xor_sync(0xffffffffu, cm, 16));
    for (int base = 0; base < cm; base += 8) {
        int2 pr = (base + lane8 < cnt) ? g_csr[s + base + lane8] : make_int2(0, 0);
        int m = min(8, cm - base);
        int j = 0;
        for (; j + 2 <= m; j += 2) {
            int   r0 = __shfl_sync(0xffffffffu, pr.x, j, 8);
            float d0 = __int_as_float(__shfl_sync(0xffffffffu, pr.y, j, 8));
            int   r1 = __shfl_sync(0xffffffffu, pr.x, j + 1, 8);
            float d1 = __int_as_float(__shfl_sync(0xffffffffu, pr.y, j + 1, 8));
            uint4 v0 = inp[(size_t)r0 * 8 + lane8];
            uint4 v1 = inp[(size_t)r1 * 8 + lane8];
            fma8(acc, v0, d0);
            fma8(acc2, v1, d1);
        }
        if (j < m) {
            int   r0 = __shfl_sync(0xffffffffu, pr.x, j, 8);
            float d0 = __int_as_float(__shfl_sync(0xffffffffu, pr.y, j, 8));
            fma8(acc, inp[(size_t)r0 * 8 + lane8], d0);
        }
    }
    const float4* b4 = (const float4*)bias;
    float4 bv0 = b4[lane8 * 2], bv1 = b4[lane8 * 2 + 1];
    float o[8];
#pragma unroll
    for (int c = 0; c < 8; c++) o[c] = fmaf(d, acc[c] + acc2[c], ((const float*)&bv0)[0]);
    // (compute with explicit bias components)
    o[0] = fmaf(d, acc[0] + acc2[0], bv0.x);
    o[1] = fmaf(d, acc[1] + acc2[1], bv0.y);
    o[2] = fmaf(d, acc[2] + acc2[2], bv0.z);
    o[3] = fmaf(d, acc[3] + acc2[3], bv0.w);
    o[4] = fmaf(d, acc[4] + acc2[4], bv1.x);
    o[5] = fmaf(d, acc[5] + acc2[5], bv1.y);
    o[6] = fmaf(d, acc[6] + acc2[6], bv1.z);
    o[7] = fmaf(d, acc[7] + acc2[7], bv1.w);
    if (relu) {
#pragma unroll
        for (int c = 0; c < 8; c++) o[c] = fmaxf(o[c], 0.f);
    }
    if (node < n) {
        float4* o4 = (float4*)out;
        o4[(size_t)node * 16 + lane8 * 2]     = make_float4(o[0], o[1], o[2], o[3]);
        o4[(size_t)node * 16 + lane8 * 2 + 1] = make_float4(o[4], o[5], o[6], o[7]);
    }
}

// ---------------- Decode: 16-lane groups (2 edges/warp), float4 loads ----------------
__global__ void k_decode(const int* __restrict__ eli, const float* __restrict__ z,
                         float* __restrict__ out, int nL) {
    int t = threadIdx.x;
    int w = blockIdx.x * 16 + (t >> 4);
    int lane16 = t & 15;
    int vw = min(w, nL - 1);
    int s = eli[vw];
    int d = eli[nL + vw];
    const float4* z4 = (const float4*)z;
    float4 a = z4[(size_t)s * 16 + lane16];
    float4 b = z4[(size_t)d * 16 + lane16];
    float p = a.x * b.x + a.y * b.y + a.z * b.z + a.w * b.w;
#pragma unroll
    for (int o = 8; o > 0; o >>= 1) p += __shfl_down_sync(0xffffffffu, p, o, 16);
    if (lane16 == 0 && w < nL) out[w] = p;
}

// ---------------- launch ----------------
extern "C" void kernel_launch(void* const* d_in, const int* in_sizes, int n_in,
                              void* d_out, int out_size) {
    const float* x   = (const float*)d_in[0];
    const int*   ei  = (const int*)  d_in[1];
    const int*   eli = (const int*)  d_in[2];
    const float* W1  = (const float*)d_in[3];
    const float* b1  = (const float*)d_in[4];
    const float* W2  = (const float*)d_in[5];
    const float* b2  = (const float*)d_in[6];
    float* out = (float*)d_out;

    int n  = in_sizes[0] / 256;
    int nE = in_sizes[1] / 2;
    int nL = in_sizes[2] / 2;

    void *p_xw1, *p_h, *p_xw2, *p_z;
    cudaGetSymbolAddress(&p_xw1, g_xw1);
    cudaGetSymbolAddress(&p_h,   g_h);
    cudaGetSymbolAddress(&p_xw2, g_xw2);
    cudaGetSymbolAddress(&p_z,   g_z);

    // Fork: CSR build on side stream, GEMM1 concurrently on main stream.
    cudaEventRecord(g_evF, 0);
    cudaStreamWaitEvent(g_s2, g_evF, 0);

    k_count<<<(nE + 255) / 256, 256, 0, g_s2>>>(ei, nE);
    int nb = (n + 1023) / 1024;
    k_scan_fused<<<nb, 1024, 0, g_s2>>>(n, nb);
    k_scatter<<<(nE + 255) / 256, 256, 0, g_s2>>>(ei, nE);
    cudaEventRecord(g_evJ, g_s2);

    int gb = (n + 127) / 128;
    k_gemm_mma<256><<<gb, 256>>>(x, W1, (__half*)p_xw1, n);   // concurrent with CSR

    // Join
    cudaStreamWaitEvent(0, g_evJ, 0);

    // layer 1 aggregate (fp16 gather -> fp32 h)
    k_aggregate<<<(n + 31) / 32, 256>>>((const __half*)p_xw1, (float*)p_h, b1, n, 1);
    // layer 2
    k_gemm_mma<64><<<gb, 256>>>((const float*)p_h, W2, (__half*)p_xw2, n);
    k_aggregate<<<(n + 31) / 32, 256>>>((const __half*)p_xw2, (float*)p_z, b2, n, 0);
    // decode
    k_decode<<<(nL + 15) / 16, 256>>>(eli, (const float*)p_z, out, nL);
}